// round 15
// baseline (speedup 1.0000x reference)
#include <cuda_runtime.h>
#include <math.h>

#define S 128
#define NRBF 20
#define DEG 16
#define BN 36
#define NCOL 18
#define NACC 9
#define SLICE 24
#define BWF 48
#define GMAX 64
#define PHI_BLOCKS 8

__device__ float g_phi[3 * S];
__device__ float g_graph[GMAX * S];
__device__ int g_flag = 0;    // phi ready counter
__device__ int g_done = 0;    // node-block completion counter
__device__ int g_done2 = 0;   // phi-block output completion counter

typedef unsigned long long ull;

#define OFF_BUFA 0
#define OFF_BUFB (S * BWF)
#define OFF_SA   (2 * S * BWF)
#define OFF_SB   (OFF_SA + BN * NRBF)
#define OFF_SAB  (OFF_SB + BN * 3 * NRBF)
#define OFF_SBB  (OFF_SAB + BN)
#define OFF_SINV (OFF_SBB + 3 * BN)
#define OFF_SCP  (OFF_SINV + BN)
#define OFF_SC   (OFF_SCP + 8 * NCOL)
#define OFF_GIDX (OFF_SC + BN)
#define SMEM_FLOATS (OFF_GIDX + BN)
#define SMEM_BYTES (SMEM_FLOATS * 4)

__device__ __forceinline__ float siluf(float x) {
    return x / (1.0f + __expf(-x));
}
__device__ __forceinline__ ull pack2(float a, float b) {
    ull r;
    asm("mov.b64 %0, {%1,%2};" : "=l"(r) : "f"(a), "f"(b));
    return r;
}
__device__ __forceinline__ ull ffma2(ull a, ull b, ull c) {
    ull d;
    asm("fma.rn.f32x2 %0, %1, %2, %3;" : "=l"(d) : "l"(a), "l"(b), "l"(c));
    return d;
}
__device__ __forceinline__ void unpack2(ull p, float& lo, float& hi) {
    asm("mov.b64 {%0,%1}, %2;" : "=f"(lo), "=f"(hi) : "l"(p));
}

__device__ __forceinline__ void load_row9(const float* base, ull* x) {
    const ulonglong2* p2 = (const ulonglong2*)base;
    ulonglong2 a = p2[0], b = p2[1], c = p2[2], d = p2[3];
    x[0] = a.x; x[1] = a.y; x[2] = b.x; x[3] = b.y;
    x[4] = c.x; x[5] = c.y; x[6] = d.x; x[7] = d.y;
    x[8] = ((const ull*)base)[8];
}

__device__ __forceinline__ float bf4x4(float q0, float q1, float q2, float q3, int le) {
    const unsigned FULL = 0xffffffffu;
    float a = (le & 1) ? q1 : q0;
    float b = (le & 1) ? q0 : q1;
    a += __shfl_xor_sync(FULL, b, 1);
    float c = (le & 1) ? q3 : q2;
    float d = (le & 1) ? q2 : q3;
    c += __shfl_xor_sync(FULL, d, 1);
    float e = (le & 2) ? c : a;
    float f = (le & 2) ? a : c;
    e += __shfl_xor_sync(FULL, f, 2);
    return e;
}

// ---------------------------------------------------------------------------
// Single mega kernel.
// Blocks 0..7: phi producer, then output MLP consumer (8 graphs each).
// Blocks 8..: node blocks (edge -> wait phi -> filter -> MLP -> atomics -> ticket).
// ---------------------------------------------------------------------------
__global__ void __launch_bounds__(256, 2) k_main(
        const float* __restrict__ diffs, const float* __restrict__ lens,
        const float* __restrict__ emb0,
        const float* __restrict__ pw1, const float* __restrict__ pb1,
        const float* __restrict__ pw2, const float* __restrict__ pb2,
        const float* __restrict__ filt_w, const float* __restrict__ filt_b,
        const float* __restrict__ u_w, const float* __restrict__ v_w,
        const float* __restrict__ w1, const float* __restrict__ b1,
        const float* __restrict__ w2, const float* __restrict__ b2,
        const float* __restrict__ ow1, const float* __restrict__ ob1,
        const float* __restrict__ ow2, const float* __restrict__ ob2,
        const int* __restrict__ gidx,
        float* __restrict__ out, int N, int G, int nblk_nodes) {
    extern __shared__ __align__(16) float sm[];
    float* bufA = sm + OFF_BUFA;
    float* bufB = sm + OFF_BUFB;
    float* sA   = sm + OFF_SA;
    float* sB   = sm + OFF_SB;
    float* sAb  = sm + OFF_SAB;
    float* sBb  = sm + OFF_SBB;
    float* sInv = sm + OFF_SINV;
    float* scp  = sm + OFF_SCP;
    float* sc   = sm + OFF_SC;
    int* sgidx  = (int*)(sm + OFF_GIDX);

    const unsigned FULL = 0xffffffffu;
    int t = threadIdx.x;
    int f = t & 127;
    int h = t >> 7;
    int colbase = NCOL * h;
    int b = blockIdx.x;

    // ======================= PHI / OUTPUT BLOCKS =======================
    if (b < PHI_BLOCKS) {
        float* se    = bufA;             // [128]
        float* part1 = bufA + 128;       // [2][128]
        float* h1s   = bufA + 384;       // [128]
        float* part2 = bufA + 512;       // [8][32]

        // zero my slice of g_graph
        for (int i = t; i < GMAX * S / PHI_BLOCKS; i += 256)
            g_graph[b * (GMAX * S / PHI_BLOCKS) + i] = 0.0f;

        if (t < S) se[t] = 128.0f * emb0[t];
        __syncthreads();
        {   // stage 1: h1, split-K x2, 8 chains
            int q = t >> 7;
            int k0 = q * 64;
            float a0 = 0, a1 = 0, a2 = 0, a3 = 0, a4 = 0, a5 = 0, a6 = 0, a7 = 0;
            #pragma unroll
            for (int i = 0; i < 64; i += 8) {
                a0 += se[k0 + i + 0] * pw1[(k0 + i + 0) * S + f];
                a1 += se[k0 + i + 1] * pw1[(k0 + i + 1) * S + f];
                a2 += se[k0 + i + 2] * pw1[(k0 + i + 2) * S + f];
                a3 += se[k0 + i + 3] * pw1[(k0 + i + 3) * S + f];
                a4 += se[k0 + i + 4] * pw1[(k0 + i + 4) * S + f];
                a5 += se[k0 + i + 5] * pw1[(k0 + i + 5) * S + f];
                a6 += se[k0 + i + 6] * pw1[(k0 + i + 6) * S + f];
                a7 += se[k0 + i + 7] * pw1[(k0 + i + 7) * S + f];
            }
            part1[q * S + f] = ((a0 + a1) + (a2 + a3)) + ((a4 + a5) + (a6 + a7));
        }
        __syncthreads();
        if (t < S) {
            float s = pb1[t] + part1[t] + part1[S + t];
            h1s[t] = s / (1.0f + expf(-s));
        }
        __syncthreads();
        {   // stage 2: 32 phi outputs for this block
            int ol = t & 31;
            int q = t >> 5;
            int o = S + b * 32 + ol;
            int k0 = q * 16;
            float a0 = 0, a1 = 0, a2 = 0, a3 = 0;
            #pragma unroll
            for (int i = 0; i < 16; i += 4) {
                a0 += h1s[k0 + i + 0] * pw2[(k0 + i + 0) * 3 * S + o];
                a1 += h1s[k0 + i + 1] * pw2[(k0 + i + 1) * 3 * S + o];
                a2 += h1s[k0 + i + 2] * pw2[(k0 + i + 2) * 3 * S + o];
                a3 += h1s[k0 + i + 3] * pw2[(k0 + i + 3) * 3 * S + o];
            }
            part2[q * 32 + ol] = (a0 + a1) + (a2 + a3);
        }
        __syncthreads();
        if (t < 32) {
            int o = S + b * 32 + t;
            float s = pb2[o];
            #pragma unroll
            for (int j = 0; j < 8; j++) s += part2[j * 32 + t];
            g_phi[o] = s;
        }
        __threadfence();
        __syncthreads();
        if (t == 0) atomicAdd(&g_flag, 1);

        // ---- wait for ALL node blocks, then output MLP for my 8 graphs ----
        if (t == 0) {
            while (*(volatile int*)&g_done < nblk_nodes) __nanosleep(256);
            __threadfence();
        }
        __syncthreads();

        float* gs = bufB;         // [2][128]
        float* red = bufB + 256;  // [2][4]
        for (int gp = 0; gp < 8; gp += 2) {
            int g = b * 8 + gp + h;
            bool gok = g < G;
            int gc = gok ? g : 0;
            // bypass L1: our zeroing stores may have left stale lines
            gs[h * S + f] = __ldcg(&g_graph[gc * S + f]);
            __syncthreads();
            float a0 = 0, a1 = 0, a2 = 0, a3 = 0;
            const float* gsr = gs + h * S;
            #pragma unroll
            for (int s = 0; s < S; s += 4) {
                a0 += gsr[s + 0] * ow1[(s + 0) * S + f];
                a1 += gsr[s + 1] * ow1[(s + 1) * S + f];
                a2 += gsr[s + 2] * ow1[(s + 2) * S + f];
                a3 += gsr[s + 3] * ow1[(s + 3) * S + f];
            }
            float hacc = ob1[f] + (a0 + a1) + (a2 + a3);
            float hh = hacc / (1.0f + expf(-hacc));
            float p = hh * ow2[f];
            #pragma unroll
            for (int m = 16; m; m >>= 1) p += __shfl_xor_sync(FULL, p, m);
            int wq = (t >> 5) & 3, lane = t & 31;
            if (lane == 0) red[h * 4 + wq] = p;
            __syncthreads();
            if (f == 0 && gok)
                out[g] = red[h * 4 + 0] + red[h * 4 + 1] + red[h * 4 + 2] +
                         red[h * 4 + 3] + ob2[0];
            __syncthreads();
        }

        // ---- reset flags for next graph replay (last phi block) ----
        __threadfence();
        if (t == 0) {
            int r = atomicAdd(&g_done2, 1);
            if (r == PHI_BLOCKS - 1) {
                g_flag = 0;
                g_done = 0;
                g_done2 = 0;
                __threadfence();
            }
        }
        return;
    }

    // ========================== NODE BLOCKS ==========================
    int n0 = (b - PHI_BLOCKS) * BN;

    if (t < BN) sgidx[t] = gidx[min(n0 + t, N - 1)];

    // ---- Edge stage: 4 lanes/node, 4 edges/lane ----
    {
        int gi = t >> 2;
        int le = t & 3;
        bool valid = gi < BN;
        int nc = min(n0 + min(gi, BN - 1), N - 1);
        int e0 = nc * DEG + le * 4;
        const float4* dp = (const float4*)(diffs + 3 * e0);
        float4 d0 = dp[0], d1 = dp[1], d2 = dp[2];
        float4 lv = *(const float4*)(lens + e0);
        float dx[4] = {d0.x, d0.w, d1.z, d2.y};
        float dy[4] = {d0.y, d1.x, d1.w, d2.z};
        float dz[4] = {d0.z, d1.y, d2.x, d2.w};
        float ln[4] = {lv.x, lv.y, lv.z, lv.w};
        float pir[4], pre[4], sk[4], skm[4], cc[4];
        float fr = 0.0f;
        #pragma unroll
        for (int j = 0; j < 4; j++) {
            float r2 = dx[j] * dx[j] + dy[j] * dy[j] + dz[j] * dz[j];
            float r = sqrtf(r2);
            float m = (fabsf(ln[j]) <= 10.0f) ? 1.0f : 0.0f;
            float rs = fmaxf(r, 1e-12f);
            float bq = rs * 0.1f;
            float c = cospif(bq);
            float s = sinpif(bq);
            float cut = (r < 10.0f) ? 0.5f * (c + 1.0f) : 0.0f;
            pre[j] = m * cut;
            pir[j] = m * cut / rs;
            sk[j] = s; skm[j] = 0.0f; cc[j] = 2.0f * c;
            fr += m * r2;
        }
        fr += __shfl_xor_sync(FULL, fr, 1);
        fr += __shfl_xor_sync(FULL, fr, 2);
        if (valid && le == 0) {
            float frob = sqrtf(fr);
            sInv[gi] = 1.0f / ((frob > 0.0f) ? frob : 1.0f);
        }
        {
            float q0 = pre[0] + pre[1] + pre[2] + pre[3];
            float q1 = pre[0] * dx[0] + pre[1] * dx[1] + pre[2] * dx[2] + pre[3] * dx[3];
            float q2 = pre[0] * dy[0] + pre[1] * dy[1] + pre[2] * dy[2] + pre[3] * dy[3];
            float q3 = pre[0] * dz[0] + pre[1] * dz[1] + pre[2] * dz[2] + pre[3] * dz[3];
            float v = bf4x4(q0, q1, q2, q3, le);
            if (valid) {
                if (le == 0) sAb[gi] = v;
                else sBb[gi * 3 + le - 1] = v;
            }
        }
        #pragma unroll
        for (int k = 0; k < NRBF; k++) {
            float a0 = pir[0] * sk[0];
            float a1 = pir[1] * sk[1];
            float a2 = pir[2] * sk[2];
            float a3 = pir[3] * sk[3];
            float q0 = (a0 + a1) + (a2 + a3);
            float q1 = a0 * dx[0] + a1 * dx[1] + a2 * dx[2] + a3 * dx[3];
            float q2 = a0 * dy[0] + a1 * dy[1] + a2 * dy[2] + a3 * dy[3];
            float q3 = a0 * dz[0] + a1 * dz[1] + a2 * dz[2] + a3 * dz[3];
            float v = bf4x4(q0, q1, q2, q3, le);
            if (valid) {
                if (le == 0) sA[gi * NRBF + k] = v;
                else sB[(gi * 3 + le - 1) * NRBF + k] = v;
            }
            #pragma unroll
            for (int j = 0; j < 4; j++) {
                float sn = cc[j] * sk[j] - skm[j];
                skm[j] = sk[j];
                sk[j] = sn;
            }
        }
    }

    // ---- wait for phi (read-only poll, no RMW convoy) ----
    if (t == 0) {
        while (*(volatile int*)&g_flag < PHI_BLOCKS) __nanosleep(64);
        __threadfence();
    }
    __syncthreads();

    // ---- Filter dots -> tiles ----
    {
        int c = f % 3;
        float phi2 = g_phi[S + f];
        float phi3 = g_phi[2 * S + f];
        float fb2 = filt_b[S + f];
        float fb3 = filt_b[2 * S + f];
        float* rowA = bufA + (f * 2 + h) * SLICE;
        float* rowB = bufB + (f * 2 + h) * SLICE;

        ull w2p[NRBF / 2], w3p[NRBF / 2];
        #pragma unroll
        for (int kk = 0; kk < NRBF / 2; kk++) {
            w2p[kk] = pack2(filt_w[(2 * kk) * 3 * S + S + f],
                            filt_w[(2 * kk + 1) * 3 * S + S + f]);
            w3p[kk] = pack2(filt_w[(2 * kk) * 3 * S + 2 * S + f],
                            filt_w[(2 * kk + 1) * 3 * S + 2 * S + f]);
        }
        #pragma unroll
        for (int ni = 0; ni < NCOL; ni += 2) {
            int col0 = colbase + ni;
            int col1 = col0 + 1;
            ull a2x = 0ull, a2y = 0ull, a3x = 0ull, a3y = 0ull;
            const ull* pa0 = (const ull*)&sA[col0 * NRBF];
            const ull* pa1 = (const ull*)&sA[col1 * NRBF];
            const ull* pb0 = (const ull*)&sB[(col0 * 3 + c) * NRBF];
            const ull* pb1 = (const ull*)&sB[(col1 * 3 + c) * NRBF];
            #pragma unroll
            for (int kk = 0; kk < NRBF / 2; kk++) {
                a2x = ffma2(pa0[kk], w2p[kk], a2x);
                a2y = ffma2(pa1[kk], w2p[kk], a2y);
                a3x = ffma2(pb0[kk], w3p[kk], a3x);
                a3y = ffma2(pb1[kk], w3p[kk], a3y);
            }
            float xl, xh, yl, yh, ul, uh, vl, vh;
            unpack2(a2x, xl, xh);
            unpack2(a2y, yl, yh);
            unpack2(a3x, ul, uh);
            unpack2(a3y, vl, vh);
            float s0 = phi2 * (xl + xh + sAb[col0] * fb2);
            float s1 = phi2 * (yl + yh + sAb[col1] * fb2);
            float v0 = phi3 * (ul + uh + sBb[col0 * 3 + c] * fb3) * sInv[col0];
            float v1 = phi3 * (vl + vh + sBb[col1 * 3 + c] * fb3) * sInv[col1];
            *(ull*)(rowB + ni) = pack2(s0, s1);
            *(ull*)(rowA + ni) = pack2(v0, v1);
        }
    }
    __syncthreads();

    // ---- U, V matmuls ----
    ull aU[NACC], aV[NACC];
    #pragma unroll
    for (int j = 0; j < NACC; j++) { aU[j] = 0ull; aV[j] = 0ull; }
    #pragma unroll 2
    for (int s = 0; s < S; s++) {
        float wu = u_w[s * S + f];
        float wv = v_w[s * S + f];
        ull wuu = pack2(wu, wu), wvv = pack2(wv, wv);
        ull x[NACC];
        load_row9(bufA + (s * 2 + h) * SLICE, x);
        #pragma unroll
        for (int j = 0; j < NACC; j++) {
            aU[j] = ffma2(x[j], wuu, aU[j]);
            aV[j] = ffma2(x[j], wvv, aV[j]);
        }
    }
    __syncthreads();

    const float SQ3 = 1.7320508075688772f;
    float prod[NCOL];
    {
        float* rowA = bufA + (f * 2 + h) * SLICE;
        #pragma unroll
        for (int j = 0; j < NACC; j++) {
            float u0, u1, v0, v1;
            unpack2(aU[j], u0, u1);
            unpack2(aV[j], v0, v1);
            prod[2 * j] = u0 * v0;
            prod[2 * j + 1] = u1 * v1;
            *(ull*)(rowA + 2 * j) = pack2(SQ3 * fabsf(v0), SQ3 * fabsf(v1));
        }
    }
    int w = t >> 5, lane = t & 31;
    #pragma unroll
    for (int ni = 0; ni < NCOL; ni++) {
        float v = prod[ni];
        #pragma unroll
        for (int m = 16; m; m >>= 1) v += __shfl_xor_sync(FULL, v, m);
        if (lane == 0) scp[w * NCOL + ni] = v;
    }
    __syncthreads();
    if (t < BN) {
        int hh = t / NCOL, ni = t % NCOL;
        int wb = hh * 4;
        sc[t] = scp[wb * NCOL + ni] + scp[(wb + 1) * NCOL + ni] +
                scp[(wb + 2) * NCOL + ni] + scp[(wb + 3) * NCOL + ni];
    }
    __syncthreads();

    // ---- h = silu([Vnorm, state1] @ upd_w1 + b1) ----
    ull aH[NACC];
    #pragma unroll
    for (int j = 0; j < NACC; j++) aH[j] = 0ull;
    #pragma unroll 2
    for (int s = 0; s < S; s++) {
        float wA = w1[s * S + f];
        float wB = w1[(S + s) * S + f];
        ull wAA = pack2(wA, wA), wBB = pack2(wB, wB);
        ull xa[NACC], xb[NACC];
        load_row9(bufA + (s * 2 + h) * SLICE, xa);
        load_row9(bufB + (s * 2 + h) * SLICE, xb);
        #pragma unroll
        for (int j = 0; j < NACC; j++) {
            aH[j] = ffma2(xa[j], wAA, aH[j]);
            aH[j] = ffma2(xb[j], wBB, aH[j]);
        }
    }
    __syncthreads();
    {
        float bb = b1[f];
        float* rowA = bufA + (f * 2 + h) * SLICE;
        #pragma unroll
        for (int j = 0; j < NACC; j++) {
            float h0, h1v;
            unpack2(aH[j], h0, h1v);
            *(ull*)(rowA + 2 * j) = pack2(siluf(h0 + bb), siluf(h1v + bb));
        }
    }
    __syncthreads();

    // ---- a_sv, a_ss; final state -> REDG into graph accumulator ----
    ull aSV[NACC], aSS[NACC];
    #pragma unroll
    for (int j = 0; j < NACC; j++) { aSV[j] = 0ull; aSS[j] = 0ull; }
    #pragma unroll 2
    for (int s = 0; s < S; s++) {
        float wsv = w2[s * 3 * S + S + f];
        float wss = w2[s * 3 * S + 2 * S + f];
        ull wv2 = pack2(wsv, wsv), ws2 = pack2(wss, wss);
        ull x[NACC];
        load_row9(bufA + (s * 2 + h) * SLICE, x);
        #pragma unroll
        for (int j = 0; j < NACC; j++) {
            aSV[j] = ffma2(x[j], wv2, aSV[j]);
            aSS[j] = ffma2(x[j], ws2, aSS[j]);
        }
    }
    {
        float bsv = b2[S + f];
        float bss = b2[2 * S + f];
        #pragma unroll
        for (int j = 0; j < NACC; j++) {
            float sv0, sv1, ss0, ss1;
            unpack2(aSV[j], sv0, sv1);
            unpack2(aSS[j], ss0, ss1);
            int col = colbase + 2 * j;
            int nn0 = n0 + col;
            if (nn0 < N) {
                float v = (ss0 + bss) + 3.0f * sc[col] * (sv0 + bsv);
                atomicAdd(&g_graph[sgidx[col] * S + f], v);
            }
            if (nn0 + 1 < N) {
                float v = (ss1 + bss) + 3.0f * sc[col + 1] * (sv1 + bsv);
                atomicAdd(&g_graph[sgidx[col + 1] * S + f], v);
            }
        }
    }

    // ---- completion ticket ----
    __threadfence();
    __syncthreads();
    if (t == 0) atomicAdd(&g_done, 1);
}

// ---------------------------------------------------------------------------
extern "C" void kernel_launch(void* const* d_in, const int* in_sizes, int n_in,
                              void* d_out, int out_size) {
    int N = in_sizes[3];
    int off = (n_in >= 22) ? 1 : 0;

    const float* diffs   = (const float*)d_in[0];
    const float* lens    = (const float*)d_in[1];
    const int*   gidx    = (const int*)d_in[3];
    const float* emb0    = (const float*)d_in[4 + off];
    const float* phi_w1  = (const float*)d_in[5 + off];
    const float* phi_b1  = (const float*)d_in[6 + off];
    const float* phi_w2  = (const float*)d_in[7 + off];
    const float* phi_b2  = (const float*)d_in[8 + off];
    const float* filt_w  = (const float*)d_in[9 + off];
    const float* filt_b  = (const float*)d_in[10 + off];
    const float* u_w     = (const float*)d_in[11 + off];
    const float* v_w     = (const float*)d_in[12 + off];
    const float* upd_w1  = (const float*)d_in[13 + off];
    const float* upd_b1  = (const float*)d_in[14 + off];
    const float* upd_w2  = (const float*)d_in[15 + off];
    const float* upd_b2  = (const float*)d_in[16 + off];
    const float* out_w1  = (const float*)d_in[17 + off];
    const float* out_b1  = (const float*)d_in[18 + off];
    const float* out_w2  = (const float*)d_in[19 + off];
    const float* out_b2  = (const float*)d_in[20 + off];
    float* out = (float*)d_out;
    int G = out_size;

    cudaFuncSetAttribute(k_main, cudaFuncAttributeMaxDynamicSharedMemorySize,
                         SMEM_BYTES);

    int nblk_nodes = (N + BN - 1) / BN;
    int nblk = nblk_nodes + PHI_BLOCKS;
    k_main<<<nblk, 256, SMEM_BYTES>>>(diffs, lens, emb0,
                                      phi_w1, phi_b1, phi_w2, phi_b2,
                                      filt_w, filt_b,
                                      u_w, v_w, upd_w1, upd_b1, upd_w2, upd_b2,
                                      out_w1, out_b1, out_w2, out_b2,
                                      gidx, out, N, G, nblk_nodes);
}

// round 16
// speedup vs baseline: 1.0826x; 1.0826x over previous
#include <cuda_runtime.h>
#include <math.h>

#define S 128
#define NRBF 20
#define DEG 16
#define BN 36         // nodes per block (278 blocks = 1 wave @ 2/SM)
#define NCOL 18       // columns per 128-thread half
#define NACC 9        // f32x2 accumulators per half
#define SLICE 24      // floats per half-row slice (96B, 16B-aligned)
#define BWF 48        // floats per row (2 slices)
#define GMAX 64
#define PHI_BLOCKS 8

__device__ float g_phi[3 * S];
__device__ float g_graph[GMAX * S];

typedef unsigned long long ull;

// dynamic smem layout (floats)
#define OFF_BUFA 0
#define OFF_BUFB (S * BWF)
#define OFF_SA   (2 * S * BWF)
#define OFF_SB   (OFF_SA + BN * NRBF)
#define OFF_SAB  (OFF_SB + BN * 3 * NRBF)
#define OFF_SBB  (OFF_SAB + BN)
#define OFF_SINV (OFF_SBB + 3 * BN)
#define OFF_SCP  (OFF_SINV + BN)
#define OFF_SC   (OFF_SCP + 8 * NCOL)
#define OFF_GIDX (OFF_SC + BN)
#define SMEM_FLOATS (OFF_GIDX + BN)
#define SMEM_BYTES (SMEM_FLOATS * 4)

__device__ __forceinline__ float siluf(float x) {
    return x / (1.0f + __expf(-x));
}
__device__ __forceinline__ ull pack2(float a, float b) {
    ull r;
    asm("mov.b64 %0, {%1,%2};" : "=l"(r) : "f"(a), "f"(b));
    return r;
}
__device__ __forceinline__ ull ffma2(ull a, ull b, ull c) {
    ull d;
    asm("fma.rn.f32x2 %0, %1, %2, %3;" : "=l"(d) : "l"(a), "l"(b), "l"(c));
    return d;
}
__device__ __forceinline__ void unpack2(ull p, float& lo, float& hi) {
    asm("mov.b64 {%0,%1}, %2;" : "=f"(lo), "=f"(hi) : "l"(p));
}

// load 18 floats (9 ulls) from a 16B-aligned slice: 4x LDS.128 + 1x LDS.64
__device__ __forceinline__ void load_row9(const float* base, ull* x) {
    const ulonglong2* p2 = (const ulonglong2*)base;
    ulonglong2 a = p2[0], b = p2[1], c = p2[2], d = p2[3];
    x[0] = a.x; x[1] = a.y; x[2] = b.x; x[3] = b.y;
    x[4] = c.x; x[5] = c.y; x[6] = d.x; x[7] = d.y;
    x[8] = ((const ull*)base)[8];
}

// 4-lane 4-channel butterfly
__device__ __forceinline__ float bf4x4(float q0, float q1, float q2, float q3, int le) {
    const unsigned FULL = 0xffffffffu;
    float a = (le & 1) ? q1 : q0;
    float b = (le & 1) ? q0 : q1;
    a += __shfl_xor_sync(FULL, b, 1);
    float c = (le & 1) ? q3 : q2;
    float d = (le & 1) ? q2 : q3;
    c += __shfl_xor_sync(FULL, d, 1);
    float e = (le & 2) ? c : a;
    float f = (le & 2) ? a : c;
    e += __shfl_xor_sync(FULL, f, 2);
    return e;
}

// ---------------------------------------------------------------------------
// Kernel 0: phi vector. 8 blocks x 1024 threads.
// ---------------------------------------------------------------------------
__global__ void __launch_bounds__(1024) k_phi(
        const float* __restrict__ emb0,
        const float* __restrict__ w1, const float* __restrict__ b1,
        const float* __restrict__ w2, const float* __restrict__ b2) {
    __shared__ float se[S];
    __shared__ float part1[8][S];
    __shared__ float h1[S];
    __shared__ float part2[32][32];
    int t = threadIdx.x;
    int b = blockIdx.x;

    for (int i = b * 1024 + t; i < GMAX * S; i += PHI_BLOCKS * 1024)
        g_graph[i] = 0.0f;

    if (t < S) se[t] = 128.0f * emb0[t];
    __syncthreads();

    {
        int f = t & 127;
        int q = t >> 7;
        int k0 = q * 16;
        float a0 = 0.0f, a1 = 0.0f, a2 = 0.0f, a3 = 0.0f;
        #pragma unroll
        for (int i = 0; i < 16; i += 4) {
            a0 += se[k0 + i + 0] * w1[(k0 + i + 0) * S + f];
            a1 += se[k0 + i + 1] * w1[(k0 + i + 1) * S + f];
            a2 += se[k0 + i + 2] * w1[(k0 + i + 2) * S + f];
            a3 += se[k0 + i + 3] * w1[(k0 + i + 3) * S + f];
        }
        part1[q][f] = (a0 + a1) + (a2 + a3);
    }
    __syncthreads();
    if (t < S) {
        float s = b1[t];
        #pragma unroll
        for (int j = 0; j < 8; j++) s += part1[j][t];
        h1[t] = s / (1.0f + expf(-s));
    }
    __syncthreads();

    {
        int ol = t & 31;
        int q = t >> 5;
        int o = S + b * 32 + ol;
        int k0 = q * 4;
        float a0 = h1[k0 + 0] * w2[(k0 + 0) * 3 * S + o]
                 + h1[k0 + 2] * w2[(k0 + 2) * 3 * S + o];
        float a1 = h1[k0 + 1] * w2[(k0 + 1) * 3 * S + o]
                 + h1[k0 + 3] * w2[(k0 + 3) * 3 * S + o];
        part2[q][ol] = a0 + a1;
    }
    __syncthreads();
    if (t < 32) {
        int o = S + b * 32 + t;
        float s = b2[o];
        #pragma unroll
        for (int j = 0; j < 32; j++) s += part2[j][t];
        g_phi[o] = s;
    }
}

// ---------------------------------------------------------------------------
// Fused kernel: edge stats + filter dots -> aligned tiles -> MLP -> atomics.
// ---------------------------------------------------------------------------
__global__ void __launch_bounds__(256, 2) k_main(
        const float* __restrict__ diffs, const float* __restrict__ lens,
        const float* __restrict__ filt_w, const float* __restrict__ filt_b,
        const float* __restrict__ u_w, const float* __restrict__ v_w,
        const float* __restrict__ w1, const float* __restrict__ b1,
        const float* __restrict__ w2, const float* __restrict__ b2,
        const int* __restrict__ gidx, int N) {
    extern __shared__ __align__(16) float sm[];
    float* bufA = sm + OFF_BUFA;
    float* bufB = sm + OFF_BUFB;
    float* sA   = sm + OFF_SA;
    float* sB   = sm + OFF_SB;
    float* sAb  = sm + OFF_SAB;
    float* sBb  = sm + OFF_SBB;
    float* sInv = sm + OFF_SINV;
    float* scp  = sm + OFF_SCP;
    float* sc   = sm + OFF_SC;
    int* sgidx  = (int*)(sm + OFF_GIDX);

    const unsigned FULL = 0xffffffffu;
    int t = threadIdx.x;
    int f = t & 127;
    int h = t >> 7;
    int colbase = NCOL * h;
    int n0 = blockIdx.x * BN;

    if (t < BN) sgidx[t] = gidx[min(n0 + t, N - 1)];

    // ---- Edge stage: 4 lanes/node, 4 edges/lane ----
    {
        int gi = t >> 2;
        int le = t & 3;
        bool valid = gi < BN;
        int nc = min(n0 + min(gi, BN - 1), N - 1);
        int e0 = nc * DEG + le * 4;
        const float4* dp = (const float4*)(diffs + 3 * e0);
        float4 d0 = dp[0], d1 = dp[1], d2 = dp[2];
        float4 lv = *(const float4*)(lens + e0);
        float dx[4] = {d0.x, d0.w, d1.z, d2.y};
        float dy[4] = {d0.y, d1.x, d1.w, d2.z};
        float dz[4] = {d0.z, d1.y, d2.x, d2.w};
        float ln[4] = {lv.x, lv.y, lv.z, lv.w};
        float pir[4], pre[4], sk[4], skm[4], cc[4];
        float fr = 0.0f;
        #pragma unroll
        for (int j = 0; j < 4; j++) {
            float r2 = dx[j] * dx[j] + dy[j] * dy[j] + dz[j] * dz[j];
            float r = sqrtf(r2);
            float m = (fabsf(ln[j]) <= 10.0f) ? 1.0f : 0.0f;
            float rs = fmaxf(r, 1e-12f);
            float bq = rs * 0.1f;
            float c = cospif(bq);
            float s = sinpif(bq);
            float cut = (r < 10.0f) ? 0.5f * (c + 1.0f) : 0.0f;
            pre[j] = m * cut;
            pir[j] = m * cut / rs;
            sk[j] = s; skm[j] = 0.0f; cc[j] = 2.0f * c;
            fr += m * r2;
        }
        fr += __shfl_xor_sync(FULL, fr, 1);
        fr += __shfl_xor_sync(FULL, fr, 2);
        if (valid && le == 0) {
            float frob = sqrtf(fr);
            sInv[gi] = 1.0f / ((frob > 0.0f) ? frob : 1.0f);
        }
        {
            float q0 = pre[0] + pre[1] + pre[2] + pre[3];
            float q1 = pre[0] * dx[0] + pre[1] * dx[1] + pre[2] * dx[2] + pre[3] * dx[3];
            float q2 = pre[0] * dy[0] + pre[1] * dy[1] + pre[2] * dy[2] + pre[3] * dy[3];
            float q3 = pre[0] * dz[0] + pre[1] * dz[1] + pre[2] * dz[2] + pre[3] * dz[3];
            float v = bf4x4(q0, q1, q2, q3, le);
            if (valid) {
                if (le == 0) sAb[gi] = v;
                else sBb[gi * 3 + le - 1] = v;
            }
        }
        #pragma unroll
        for (int k = 0; k < NRBF; k++) {
            float a0 = pir[0] * sk[0];
            float a1 = pir[1] * sk[1];
            float a2 = pir[2] * sk[2];
            float a3 = pir[3] * sk[3];
            float q0 = (a0 + a1) + (a2 + a3);
            float q1 = a0 * dx[0] + a1 * dx[1] + a2 * dx[2] + a3 * dx[3];
            float q2 = a0 * dy[0] + a1 * dy[1] + a2 * dy[2] + a3 * dy[3];
            float q3 = a0 * dz[0] + a1 * dz[1] + a2 * dz[2] + a3 * dz[3];
            float v = bf4x4(q0, q1, q2, q3, le);
            if (valid) {
                if (le == 0) sA[gi * NRBF + k] = v;
                else sB[(gi * 3 + le - 1) * NRBF + k] = v;
            }
            #pragma unroll
            for (int j = 0; j < 4; j++) {
                float sn = cc[j] * sk[j] - skm[j];
                skm[j] = sk[j];
                sk[j] = sn;
            }
        }
    }
    __syncthreads();

    // ---- Filter dots -> tiles (pairs, packed STS.64) ----
    {
        int c = f % 3;
        float phi2 = g_phi[S + f];
        float phi3 = g_phi[2 * S + f];
        float fb2 = filt_b[S + f];
        float fb3 = filt_b[2 * S + f];
        float* rowA = bufA + (f * 2 + h) * SLICE;
        float* rowB = bufB + (f * 2 + h) * SLICE;

        ull w2p[NRBF / 2], w3p[NRBF / 2];
        #pragma unroll
        for (int kk = 0; kk < NRBF / 2; kk++) {
            w2p[kk] = pack2(filt_w[(2 * kk) * 3 * S + S + f],
                            filt_w[(2 * kk + 1) * 3 * S + S + f]);
            w3p[kk] = pack2(filt_w[(2 * kk) * 3 * S + 2 * S + f],
                            filt_w[(2 * kk + 1) * 3 * S + 2 * S + f]);
        }
        #pragma unroll
        for (int ni = 0; ni < NCOL; ni += 2) {
            int col0 = colbase + ni;
            int col1 = col0 + 1;
            ull a2x = 0ull, a2y = 0ull, a3x = 0ull, a3y = 0ull;
            const ull* pa0 = (const ull*)&sA[col0 * NRBF];
            const ull* pa1 = (const ull*)&sA[col1 * NRBF];
            const ull* pb0 = (const ull*)&sB[(col0 * 3 + c) * NRBF];
            const ull* pb1 = (const ull*)&sB[(col1 * 3 + c) * NRBF];
            #pragma unroll
            for (int kk = 0; kk < NRBF / 2; kk++) {
                a2x = ffma2(pa0[kk], w2p[kk], a2x);
                a2y = ffma2(pa1[kk], w2p[kk], a2y);
                a3x = ffma2(pb0[kk], w3p[kk], a3x);
                a3y = ffma2(pb1[kk], w3p[kk], a3y);
            }
            float xl, xh, yl, yh, ul, uh, vl, vh;
            unpack2(a2x, xl, xh);
            unpack2(a2y, yl, yh);
            unpack2(a3x, ul, uh);
            unpack2(a3y, vl, vh);
            float s0 = phi2 * (xl + xh + sAb[col0] * fb2);
            float s1 = phi2 * (yl + yh + sAb[col1] * fb2);
            float v0 = phi3 * (ul + uh + sBb[col0 * 3 + c] * fb3) * sInv[col0];
            float v1 = phi3 * (vl + vh + sBb[col1 * 3 + c] * fb3) * sInv[col1];
            *(ull*)(rowB + ni) = pack2(s0, s1);
            *(ull*)(rowA + ni) = pack2(v0, v1);
        }
    }
    __syncthreads();

    // ---- U, V matmuls (unroll 4: 8 weight LDGs in flight) ----
    ull aU[NACC], aV[NACC];
    #pragma unroll
    for (int j = 0; j < NACC; j++) { aU[j] = 0ull; aV[j] = 0ull; }
    #pragma unroll 4
    for (int s = 0; s < S; s++) {
        float wu = u_w[s * S + f];
        float wv = v_w[s * S + f];
        ull wuu = pack2(wu, wu), wvv = pack2(wv, wv);
        ull x[NACC];
        load_row9(bufA + (s * 2 + h) * SLICE, x);
        #pragma unroll
        for (int j = 0; j < NACC; j++) {
            aU[j] = ffma2(x[j], wuu, aU[j]);
            aV[j] = ffma2(x[j], wvv, aV[j]);
        }
    }
    __syncthreads();

    const float SQ3 = 1.7320508075688772f;
    float prod[NCOL];
    {
        float* rowA = bufA + (f * 2 + h) * SLICE;
        #pragma unroll
        for (int j = 0; j < NACC; j++) {
            float u0, u1, v0, v1;
            unpack2(aU[j], u0, u1);
            unpack2(aV[j], v0, v1);
            prod[2 * j] = u0 * v0;
            prod[2 * j + 1] = u1 * v1;
            *(ull*)(rowA + 2 * j) = pack2(SQ3 * fabsf(v0), SQ3 * fabsf(v1));
        }
    }
    int w = t >> 5, lane = t & 31;
    #pragma unroll
    for (int ni = 0; ni < NCOL; ni++) {
        float v = prod[ni];
        #pragma unroll
        for (int m = 16; m; m >>= 1) v += __shfl_xor_sync(FULL, v, m);
        if (lane == 0) scp[w * NCOL + ni] = v;
    }
    __syncthreads();
    if (t < BN) {
        int hh = t / NCOL, ni = t % NCOL;
        int wb = hh * 4;
        sc[t] = scp[wb * NCOL + ni] + scp[(wb + 1) * NCOL + ni] +
                scp[(wb + 2) * NCOL + ni] + scp[(wb + 3) * NCOL + ni];
    }
    __syncthreads();

    // ---- h = silu([Vnorm, state1] @ upd_w1 + b1) ----
    ull aH[NACC];
    #pragma unroll
    for (int j = 0; j < NACC; j++) aH[j] = 0ull;
    #pragma unroll 2
    for (int s = 0; s < S; s++) {
        float wA = w1[s * S + f];
        float wB = w1[(S + s) * S + f];
        ull wAA = pack2(wA, wA), wBB = pack2(wB, wB);
        ull xa[NACC], xb[NACC];
        load_row9(bufA + (s * 2 + h) * SLICE, xa);
        load_row9(bufB + (s * 2 + h) * SLICE, xb);
        #pragma unroll
        for (int j = 0; j < NACC; j++) {
            aH[j] = ffma2(xa[j], wAA, aH[j]);
            aH[j] = ffma2(xb[j], wBB, aH[j]);
        }
    }
    __syncthreads();
    {
        float bb = b1[f];
        float* rowA = bufA + (f * 2 + h) * SLICE;
        #pragma unroll
        for (int j = 0; j < NACC; j++) {
            float h0, h1v;
            unpack2(aH[j], h0, h1v);
            *(ull*)(rowA + 2 * j) = pack2(siluf(h0 + bb), siluf(h1v + bb));
        }
    }
    __syncthreads();

    // ---- a_sv, a_ss; final state -> REDG into graph accumulator (unroll 4) ----
    ull aSV[NACC], aSS[NACC];
    #pragma unroll
    for (int j = 0; j < NACC; j++) { aSV[j] = 0ull; aSS[j] = 0ull; }
    #pragma unroll 4
    for (int s = 0; s < S; s++) {
        float wsv = w2[s * 3 * S + S + f];
        float wss = w2[s * 3 * S + 2 * S + f];
        ull wv2 = pack2(wsv, wsv), ws2 = pack2(wss, wss);
        ull x[NACC];
        load_row9(bufA + (s * 2 + h) * SLICE, x);
        #pragma unroll
        for (int j = 0; j < NACC; j++) {
            aSV[j] = ffma2(x[j], wv2, aSV[j]);
            aSS[j] = ffma2(x[j], ws2, aSS[j]);
        }
    }
    {
        float bsv = b2[S + f];
        float bss = b2[2 * S + f];
        #pragma unroll
        for (int j = 0; j < NACC; j++) {
            float sv0, sv1, ss0, ss1;
            unpack2(aSV[j], sv0, sv1);
            unpack2(aSS[j], ss0, ss1);
            int col = colbase + 2 * j;
            int nn0 = n0 + col;
            if (nn0 < N) {
                float v = (ss0 + bss) + 3.0f * sc[col] * (sv0 + bsv);
                atomicAdd(&g_graph[sgidx[col] * S + f], v);
            }
            if (nn0 + 1 < N) {
                float v = (ss1 + bss) + 3.0f * sc[col + 1] * (sv1 + bsv);
                atomicAdd(&g_graph[sgidx[col + 1] * S + f], v);
            }
        }
    }
}

// ---------------------------------------------------------------------------
// Output MLP per graph: 512 threads, split-K x4, 4 chains
// ---------------------------------------------------------------------------
__global__ void __launch_bounds__(512) k_out(
        const float* __restrict__ w1, const float* __restrict__ b1,
        const float* __restrict__ w2, const float* __restrict__ b2,
        float* __restrict__ out) {
    __shared__ float gs[S];
    __shared__ float part[4][S];
    __shared__ float red[4];
    int g = blockIdx.x, t = threadIdx.x;
    int f = t & 127;
    int q = t >> 7;
    if (t < S) gs[t] = g_graph[g * S + t];
    __syncthreads();
    int sbase = q * 32;
    float a0 = 0.0f, a1 = 0.0f, a2 = 0.0f, a3 = 0.0f;
    #pragma unroll
    for (int i = 0; i < 32; i += 4) {
        a0 += gs[sbase + i + 0] * w1[(sbase + i + 0) * S + f];
        a1 += gs[sbase + i + 1] * w1[(sbase + i + 1) * S + f];
        a2 += gs[sbase + i + 2] * w1[(sbase + i + 2) * S + f];
        a3 += gs[sbase + i + 3] * w1[(sbase + i + 3) * S + f];
    }
    part[q][f] = (a0 + a1) + (a2 + a3);
    __syncthreads();
    if (t < S) {
        float hacc = b1[t] + (part[0][t] + part[1][t]) + (part[2][t] + part[3][t]);
        float h = hacc / (1.0f + expf(-hacc));
        float p = h * w2[t];
        #pragma unroll
        for (int m = 16; m; m >>= 1) p += __shfl_xor_sync(0xffffffffu, p, m);
        int w = t >> 5, lane = t & 31;
        if (lane == 0) red[w] = p;
    }
    __syncthreads();
    if (t == 0) out[g] = red[0] + red[1] + red[2] + red[3] + b2[0];
}

// ---------------------------------------------------------------------------
extern "C" void kernel_launch(void* const* d_in, const int* in_sizes, int n_in,
                              void* d_out, int out_size) {
    int N = in_sizes[3];
    int off = (n_in >= 22) ? 1 : 0;

    const float* diffs   = (const float*)d_in[0];
    const float* lens    = (const float*)d_in[1];
    const int*   gidx    = (const int*)d_in[3];
    const float* emb0    = (const float*)d_in[4 + off];
    const float* phi_w1  = (const float*)d_in[5 + off];
    const float* phi_b1  = (const float*)d_in[6 + off];
    const float* phi_w2  = (const float*)d_in[7 + off];
    const float* phi_b2  = (const float*)d_in[8 + off];
    const float* filt_w  = (const float*)d_in[9 + off];
    const float* filt_b  = (const float*)d_in[10 + off];
    const float* u_w     = (const float*)d_in[11 + off];
    const float* v_w     = (const float*)d_in[12 + off];
    const float* upd_w1  = (const float*)d_in[13 + off];
    const float* upd_b1  = (const float*)d_in[14 + off];
    const float* upd_w2  = (const float*)d_in[15 + off];
    const float* upd_b2  = (const float*)d_in[16 + off];
    const float* out_w1  = (const float*)d_in[17 + off];
    const float* out_b1  = (const float*)d_in[18 + off];
    const float* out_w2  = (const float*)d_in[19 + off];
    const float* out_b2  = (const float*)d_in[20 + off];
    float* out = (float*)d_out;
    int G = out_size;

    cudaFuncSetAttribute(k_main, cudaFuncAttributeMaxDynamicSharedMemorySize,
                         SMEM_BYTES);

    k_phi<<<PHI_BLOCKS, 1024>>>(emb0, phi_w1, phi_b1, phi_w2, phi_b2);

    int nblk = (N + BN - 1) / BN;
    k_main<<<nblk, 256, SMEM_BYTES>>>(diffs, lens, filt_w, filt_b,
                                      u_w, v_w, upd_w1, upd_b1, upd_w2, upd_b2,
                                      gidx, N);

    k_out<<<G, 512>>>(out_w1, out_b1, out_w2, out_b2, out);
}

// round 17
// speedup vs baseline: 1.1112x; 1.0264x over previous
#include <cuda_runtime.h>
#include <math.h>

#define S 128
#define NRBF 20
#define DEG 16
#define BN 36         // nodes per block (278 blocks, 1 wave @ 3/SM)
#define NCOL 18       // columns per 128-thread half
#define NACC 9        // f32x2 accumulators per half
#define SLICE 24      // floats per half-row slice (96B, 16B-aligned)
#define BWF 48        // floats per row (2 slices)
#define GMAX 64
#define PHI_BLOCKS 8

__device__ float g_phi[3 * S];
__device__ float g_graph[GMAX * S];

typedef unsigned long long ull;

// dynamic smem layout (floats)
#define OFF_BUFA 0
#define OFF_BUFB (S * BWF)
#define OFF_SA   (2 * S * BWF)
#define OFF_SB   (OFF_SA + BN * NRBF)
#define OFF_SAB  (OFF_SB + BN * 3 * NRBF)
#define OFF_SBB  (OFF_SAB + BN)
#define OFF_SINV (OFF_SBB + 3 * BN)
#define OFF_SCP  (OFF_SINV + BN)
#define OFF_SC   (OFF_SCP + 8 * NCOL)
#define OFF_GIDX (OFF_SC + BN)
#define SMEM_FLOATS (OFF_GIDX + BN)
#define SMEM_BYTES (SMEM_FLOATS * 4)

__device__ __forceinline__ float siluf(float x) {
    return x / (1.0f + __expf(-x));
}
__device__ __forceinline__ ull pack2(float a, float b) {
    ull r;
    asm("mov.b64 %0, {%1,%2};" : "=l"(r) : "f"(a), "f"(b));
    return r;
}
__device__ __forceinline__ ull ffma2(ull a, ull b, ull c) {
    ull d;
    asm("fma.rn.f32x2 %0, %1, %2, %3;" : "=l"(d) : "l"(a), "l"(b), "l"(c));
    return d;
}
__device__ __forceinline__ void unpack2(ull p, float& lo, float& hi) {
    asm("mov.b64 {%0,%1}, %2;" : "=f"(lo), "=f"(hi) : "l"(p));
}

// load 18 floats (9 ulls) from a 16B-aligned slice: 4x LDS.128 + 1x LDS.64
__device__ __forceinline__ void load_row9(const float* base, ull* x) {
    const ulonglong2* p2 = (const ulonglong2*)base;
    ulonglong2 a = p2[0], b = p2[1], c = p2[2], d = p2[3];
    x[0] = a.x; x[1] = a.y; x[2] = b.x; x[3] = b.y;
    x[4] = c.x; x[5] = c.y; x[6] = d.x; x[7] = d.y;
    x[8] = ((const ull*)base)[8];
}

// 4-lane 4-channel butterfly
__device__ __forceinline__ float bf4x4(float q0, float q1, float q2, float q3, int le) {
    const unsigned FULL = 0xffffffffu;
    float a = (le & 1) ? q1 : q0;
    float b = (le & 1) ? q0 : q1;
    a += __shfl_xor_sync(FULL, b, 1);
    float c = (le & 1) ? q3 : q2;
    float d = (le & 1) ? q2 : q3;
    c += __shfl_xor_sync(FULL, d, 1);
    float e = (le & 2) ? c : a;
    float f = (le & 2) ? a : c;
    e += __shfl_xor_sync(FULL, f, 2);
    return e;
}

// ---------------------------------------------------------------------------
// Kernel 0: phi vector. 8 blocks x 1024 threads.
// ---------------------------------------------------------------------------
__global__ void __launch_bounds__(1024) k_phi(
        const float* __restrict__ emb0,
        const float* __restrict__ w1, const float* __restrict__ b1,
        const float* __restrict__ w2, const float* __restrict__ b2) {
    __shared__ float se[S];
    __shared__ float part1[8][S];
    __shared__ float h1[S];
    __shared__ float part2[32][32];
    int t = threadIdx.x;
    int b = blockIdx.x;

    for (int i = b * 1024 + t; i < GMAX * S; i += PHI_BLOCKS * 1024)
        g_graph[i] = 0.0f;

    if (t < S) se[t] = 128.0f * emb0[t];
    __syncthreads();

    {
        int f = t & 127;
        int q = t >> 7;
        int k0 = q * 16;
        float a0 = 0.0f, a1 = 0.0f, a2 = 0.0f, a3 = 0.0f;
        #pragma unroll
        for (int i = 0; i < 16; i += 4) {
            a0 += se[k0 + i + 0] * w1[(k0 + i + 0) * S + f];
            a1 += se[k0 + i + 1] * w1[(k0 + i + 1) * S + f];
            a2 += se[k0 + i + 2] * w1[(k0 + i + 2) * S + f];
            a3 += se[k0 + i + 3] * w1[(k0 + i + 3) * S + f];
        }
        part1[q][f] = (a0 + a1) + (a2 + a3);
    }
    __syncthreads();
    if (t < S) {
        float s = b1[t];
        #pragma unroll
        for (int j = 0; j < 8; j++) s += part1[j][t];
        h1[t] = s / (1.0f + expf(-s));
    }
    __syncthreads();

    {
        int ol = t & 31;
        int q = t >> 5;
        int o = S + b * 32 + ol;
        int k0 = q * 4;
        float a0 = h1[k0 + 0] * w2[(k0 + 0) * 3 * S + o]
                 + h1[k0 + 2] * w2[(k0 + 2) * 3 * S + o];
        float a1 = h1[k0 + 1] * w2[(k0 + 1) * 3 * S + o]
                 + h1[k0 + 3] * w2[(k0 + 3) * 3 * S + o];
        part2[q][ol] = a0 + a1;
    }
    __syncthreads();
    if (t < 32) {
        int o = S + b * 32 + t;
        float s = b2[o];
        #pragma unroll
        for (int j = 0; j < 32; j++) s += part2[j][t];
        g_phi[o] = s;
    }
}

// ---------------------------------------------------------------------------
// Fused kernel: edge stats + filter dots -> aligned tiles -> MLP -> atomics.
// 3 blocks/SM for occupancy.
// ---------------------------------------------------------------------------
__global__ void __launch_bounds__(256, 3) k_main(
        const float* __restrict__ diffs, const float* __restrict__ lens,
        const float* __restrict__ filt_w, const float* __restrict__ filt_b,
        const float* __restrict__ u_w, const float* __restrict__ v_w,
        const float* __restrict__ w1, const float* __restrict__ b1,
        const float* __restrict__ w2, const float* __restrict__ b2,
        const int* __restrict__ gidx, int N) {
    extern __shared__ __align__(16) float sm[];
    float* bufA = sm + OFF_BUFA;
    float* bufB = sm + OFF_BUFB;
    float* sA   = sm + OFF_SA;
    float* sB   = sm + OFF_SB;
    float* sAb  = sm + OFF_SAB;
    float* sBb  = sm + OFF_SBB;
    float* sInv = sm + OFF_SINV;
    float* scp  = sm + OFF_SCP;
    float* sc   = sm + OFF_SC;
    int* sgidx  = (int*)(sm + OFF_GIDX);

    const unsigned FULL = 0xffffffffu;
    int t = threadIdx.x;
    int f = t & 127;
    int h = t >> 7;
    int colbase = NCOL * h;
    int n0 = blockIdx.x * BN;

    if (t < BN) sgidx[t] = gidx[min(n0 + t, N - 1)];

    // ---- Edge stage: 4 lanes/node, 4 edges/lane ----
    {
        int gi = t >> 2;
        int le = t & 3;
        bool valid = gi < BN;
        int nc = min(n0 + min(gi, BN - 1), N - 1);
        int e0 = nc * DEG + le * 4;
        const float4* dp = (const float4*)(diffs + 3 * e0);
        float4 d0 = dp[0], d1 = dp[1], d2 = dp[2];
        float4 lv = *(const float4*)(lens + e0);
        float dx[4] = {d0.x, d0.w, d1.z, d2.y};
        float dy[4] = {d0.y, d1.x, d1.w, d2.z};
        float dz[4] = {d0.z, d1.y, d2.x, d2.w};
        float ln[4] = {lv.x, lv.y, lv.z, lv.w};
        float pir[4], pre[4], sk[4], skm[4], cc[4];
        float fr = 0.0f;
        #pragma unroll
        for (int j = 0; j < 4; j++) {
            float r2 = dx[j] * dx[j] + dy[j] * dy[j] + dz[j] * dz[j];
            float r = sqrtf(r2);
            float m = (fabsf(ln[j]) <= 10.0f) ? 1.0f : 0.0f;
            float rs = fmaxf(r, 1e-12f);
            float bq = rs * 0.1f;
            float c = cospif(bq);
            float s = sinpif(bq);
            float cut = (r < 10.0f) ? 0.5f * (c + 1.0f) : 0.0f;
            pre[j] = m * cut;
            pir[j] = m * cut / rs;
            sk[j] = s; skm[j] = 0.0f; cc[j] = 2.0f * c;
            fr += m * r2;
        }
        fr += __shfl_xor_sync(FULL, fr, 1);
        fr += __shfl_xor_sync(FULL, fr, 2);
        if (valid && le == 0) {
            float frob = sqrtf(fr);
            sInv[gi] = 1.0f / ((frob > 0.0f) ? frob : 1.0f);
        }
        {
            float q0 = pre[0] + pre[1] + pre[2] + pre[3];
            float q1 = pre[0] * dx[0] + pre[1] * dx[1] + pre[2] * dx[2] + pre[3] * dx[3];
            float q2 = pre[0] * dy[0] + pre[1] * dy[1] + pre[2] * dy[2] + pre[3] * dy[3];
            float q3 = pre[0] * dz[0] + pre[1] * dz[1] + pre[2] * dz[2] + pre[3] * dz[3];
            float v = bf4x4(q0, q1, q2, q3, le);
            if (valid) {
                if (le == 0) sAb[gi] = v;
                else sBb[gi * 3 + le - 1] = v;
            }
        }
        #pragma unroll
        for (int k = 0; k < NRBF; k++) {
            float a0 = pir[0] * sk[0];
            float a1 = pir[1] * sk[1];
            float a2 = pir[2] * sk[2];
            float a3 = pir[3] * sk[3];
            float q0 = (a0 + a1) + (a2 + a3);
            float q1 = a0 * dx[0] + a1 * dx[1] + a2 * dx[2] + a3 * dx[3];
            float q2 = a0 * dy[0] + a1 * dy[1] + a2 * dy[2] + a3 * dy[3];
            float q3 = a0 * dz[0] + a1 * dz[1] + a2 * dz[2] + a3 * dz[3];
            float v = bf4x4(q0, q1, q2, q3, le);
            if (valid) {
                if (le == 0) sA[gi * NRBF + k] = v;
                else sB[(gi * 3 + le - 1) * NRBF + k] = v;
            }
            #pragma unroll
            for (int j = 0; j < 4; j++) {
                float sn = cc[j] * sk[j] - skm[j];
                skm[j] = sk[j];
                sk[j] = sn;
            }
        }
    }
    __syncthreads();

    // ---- Filter dots -> tiles (pairs, packed STS.64) ----
    {
        int c = f % 3;
        float phi2 = g_phi[S + f];
        float phi3 = g_phi[2 * S + f];
        float fb2 = filt_b[S + f];
        float fb3 = filt_b[2 * S + f];
        float* rowA = bufA + (f * 2 + h) * SLICE;
        float* rowB = bufB + (f * 2 + h) * SLICE;

        ull w2p[NRBF / 2], w3p[NRBF / 2];
        #pragma unroll
        for (int kk = 0; kk < NRBF / 2; kk++) {
            w2p[kk] = pack2(filt_w[(2 * kk) * 3 * S + S + f],
                            filt_w[(2 * kk + 1) * 3 * S + S + f]);
            w3p[kk] = pack2(filt_w[(2 * kk) * 3 * S + 2 * S + f],
                            filt_w[(2 * kk + 1) * 3 * S + 2 * S + f]);
        }
        #pragma unroll
        for (int ni = 0; ni < NCOL; ni += 2) {
            int col0 = colbase + ni;
            int col1 = col0 + 1;
            ull a2x = 0ull, a2y = 0ull, a3x = 0ull, a3y = 0ull;
            const ull* pa0 = (const ull*)&sA[col0 * NRBF];
            const ull* pa1 = (const ull*)&sA[col1 * NRBF];
            const ull* pb0 = (const ull*)&sB[(col0 * 3 + c) * NRBF];
            const ull* pb1 = (const ull*)&sB[(col1 * 3 + c) * NRBF];
            #pragma unroll
            for (int kk = 0; kk < NRBF / 2; kk++) {
                a2x = ffma2(pa0[kk], w2p[kk], a2x);
                a2y = ffma2(pa1[kk], w2p[kk], a2y);
                a3x = ffma2(pb0[kk], w3p[kk], a3x);
                a3y = ffma2(pb1[kk], w3p[kk], a3y);
            }
            float xl, xh, yl, yh, ul, uh, vl, vh;
            unpack2(a2x, xl, xh);
            unpack2(a2y, yl, yh);
            unpack2(a3x, ul, uh);
            unpack2(a3y, vl, vh);
            float s0 = phi2 * (xl + xh + sAb[col0] * fb2);
            float s1 = phi2 * (yl + yh + sAb[col1] * fb2);
            float v0 = phi3 * (ul + uh + sBb[col0 * 3 + c] * fb3) * sInv[col0];
            float v1 = phi3 * (vl + vh + sBb[col1 * 3 + c] * fb3) * sInv[col1];
            *(ull*)(rowB + ni) = pack2(s0, s1);
            *(ull*)(rowA + ni) = pack2(v0, v1);
        }
    }
    __syncthreads();

    // ---- U, V matmuls ----
    ull aU[NACC], aV[NACC];
    #pragma unroll
    for (int j = 0; j < NACC; j++) { aU[j] = 0ull; aV[j] = 0ull; }
    #pragma unroll 2
    for (int s = 0; s < S; s++) {
        float wu = u_w[s * S + f];
        float wv = v_w[s * S + f];
        ull wuu = pack2(wu, wu), wvv = pack2(wv, wv);
        ull x[NACC];
        load_row9(bufA + (s * 2 + h) * SLICE, x);
        #pragma unroll
        for (int j = 0; j < NACC; j++) {
            aU[j] = ffma2(x[j], wuu, aU[j]);
            aV[j] = ffma2(x[j], wvv, aV[j]);
        }
    }
    __syncthreads();

    const float SQ3 = 1.7320508075688772f;
    float prod[NCOL];
    {
        float* rowA = bufA + (f * 2 + h) * SLICE;
        #pragma unroll
        for (int j = 0; j < NACC; j++) {
            float u0, u1, v0, v1;
            unpack2(aU[j], u0, u1);
            unpack2(aV[j], v0, v1);
            prod[2 * j] = u0 * v0;
            prod[2 * j + 1] = u1 * v1;
            *(ull*)(rowA + 2 * j) = pack2(SQ3 * fabsf(v0), SQ3 * fabsf(v1));
        }
    }
    int w = t >> 5, lane = t & 31;
    #pragma unroll
    for (int ni = 0; ni < NCOL; ni++) {
        float v = prod[ni];
        #pragma unroll
        for (int m = 16; m; m >>= 1) v += __shfl_xor_sync(FULL, v, m);
        if (lane == 0) scp[w * NCOL + ni] = v;
    }
    __syncthreads();
    if (t < BN) {
        int hh = t / NCOL, ni = t % NCOL;
        int wb = hh * 4;
        sc[t] = scp[wb * NCOL + ni] + scp[(wb + 1) * NCOL + ni] +
                scp[(wb + 2) * NCOL + ni] + scp[(wb + 3) * NCOL + ni];
    }
    __syncthreads();

    // ---- h = silu([Vnorm, state1] @ upd_w1 + b1) ----
    ull aH[NACC];
    #pragma unroll
    for (int j = 0; j < NACC; j++) aH[j] = 0ull;
    #pragma unroll 2
    for (int s = 0; s < S; s++) {
        float wA = w1[s * S + f];
        float wB = w1[(S + s) * S + f];
        ull wAA = pack2(wA, wA), wBB = pack2(wB, wB);
        ull xa[NACC], xb[NACC];
        load_row9(bufA + (s * 2 + h) * SLICE, xa);
        load_row9(bufB + (s * 2 + h) * SLICE, xb);
        #pragma unroll
        for (int j = 0; j < NACC; j++) {
            aH[j] = ffma2(xa[j], wAA, aH[j]);
            aH[j] = ffma2(xb[j], wBB, aH[j]);
        }
    }
    __syncthreads();
    {
        float bb = b1[f];
        float* rowA = bufA + (f * 2 + h) * SLICE;
        #pragma unroll
        for (int j = 0; j < NACC; j++) {
            float h0, h1v;
            unpack2(aH[j], h0, h1v);
            *(ull*)(rowA + 2 * j) = pack2(siluf(h0 + bb), siluf(h1v + bb));
        }
    }
    __syncthreads();

    // ---- a_sv, a_ss; final state -> REDG into graph accumulator ----
    ull aSV[NACC], aSS[NACC];
    #pragma unroll
    for (int j = 0; j < NACC; j++) { aSV[j] = 0ull; aSS[j] = 0ull; }
    #pragma unroll 2
    for (int s = 0; s < S; s++) {
        float wsv = w2[s * 3 * S + S + f];
        float wss = w2[s * 3 * S + 2 * S + f];
        ull wv2 = pack2(wsv, wsv), ws2 = pack2(wss, wss);
        ull x[NACC];
        load_row9(bufA + (s * 2 + h) * SLICE, x);
        #pragma unroll
        for (int j = 0; j < NACC; j++) {
            aSV[j] = ffma2(x[j], wv2, aSV[j]);
            aSS[j] = ffma2(x[j], ws2, aSS[j]);
        }
    }
    {
        float bsv = b2[S + f];
        float bss = b2[2 * S + f];
        #pragma unroll
        for (int j = 0; j < NACC; j++) {
            float sv0, sv1, ss0, ss1;
            unpack2(aSV[j], sv0, sv1);
            unpack2(aSS[j], ss0, ss1);
            int col = colbase + 2 * j;
            int nn0 = n0 + col;
            if (nn0 < N) {
                float v = (ss0 + bss) + 3.0f * sc[col] * (sv0 + bsv);
                atomicAdd(&g_graph[sgidx[col] * S + f], v);
            }
            if (nn0 + 1 < N) {
                float v = (ss1 + bss) + 3.0f * sc[col + 1] * (sv1 + bsv);
                atomicAdd(&g_graph[sgidx[col + 1] * S + f], v);
            }
        }
    }
}

// ---------------------------------------------------------------------------
// Output MLP per graph: 512 threads, split-K x4, 4 chains
// ---------------------------------------------------------------------------
__global__ void __launch_bounds__(512) k_out(
        const float* __restrict__ w1, const float* __restrict__ b1,
        const float* __restrict__ w2, const float* __restrict__ b2,
        float* __restrict__ out) {
    __shared__ float gs[S];
    __shared__ float part[4][S];
    __shared__ float red[4];
    int g = blockIdx.x, t = threadIdx.x;
    int f = t & 127;
    int q = t >> 7;
    if (t < S) gs[t] = g_graph[g * S + t];
    __syncthreads();
    int sbase = q * 32;
    float a0 = 0.0f, a1 = 0.0f, a2 = 0.0f, a3 = 0.0f;
    #pragma unroll
    for (int i = 0; i < 32; i += 4) {
        a0 += gs[sbase + i + 0] * w1[(sbase + i + 0) * S + f];
        a1 += gs[sbase + i + 1] * w1[(sbase + i + 1) * S + f];
        a2 += gs[sbase + i + 2] * w1[(sbase + i + 2) * S + f];
        a3 += gs[sbase + i + 3] * w1[(sbase + i + 3) * S + f];
    }
    part[q][f] = (a0 + a1) + (a2 + a3);
    __syncthreads();
    if (t < S) {
        float hacc = b1[t] + (part[0][t] + part[1][t]) + (part[2][t] + part[3][t]);
        float h = hacc / (1.0f + expf(-hacc));
        float p = h * w2[t];
        #pragma unroll
        for (int m = 16; m; m >>= 1) p += __shfl_xor_sync(0xffffffffu, p, m);
        int w = t >> 5, lane = t & 31;
        if (lane == 0) red[w] = p;
    }
    __syncthreads();
    if (t == 0) out[g] = red[0] + red[1] + red[2] + red[3] + b2[0];
}

// ---------------------------------------------------------------------------
extern "C" void kernel_launch(void* const* d_in, const int* in_sizes, int n_in,
                              void* d_out, int out_size) {
    int N = in_sizes[3];
    int off = (n_in >= 22) ? 1 : 0;

    const float* diffs   = (const float*)d_in[0];
    const float* lens    = (const float*)d_in[1];
    const int*   gidx    = (const int*)d_in[3];
    const float* emb0    = (const float*)d_in[4 + off];
    const float* phi_w1  = (const float*)d_in[5 + off];
    const float* phi_b1  = (const float*)d_in[6 + off];
    const float* phi_w2  = (const float*)d_in[7 + off];
    const float* phi_b2  = (const float*)d_in[8 + off];
    const float* filt_w  = (const float*)d_in[9 + off];
    const float* filt_b  = (const float*)d_in[10 + off];
    const float* u_w     = (const float*)d_in[11 + off];
    const float* v_w     = (const float*)d_in[12 + off];
    const float* upd_w1  = (const float*)d_in[13 + off];
    const float* upd_b1  = (const float*)d_in[14 + off];
    const float* upd_w2  = (const float*)d_in[15 + off];
    const float* upd_b2  = (const float*)d_in[16 + off];
    const float* out_w1  = (const float*)d_in[17 + off];
    const float* out_b1  = (const float*)d_in[18 + off];
    const float* out_w2  = (const float*)d_in[19 + off];
    const float* out_b2  = (const float*)d_in[20 + off];
    float* out = (float*)d_out;
    int G = out_size;

    cudaFuncSetAttribute(k_main, cudaFuncAttributeMaxDynamicSharedMemorySize,
                         SMEM_BYTES);

    k_phi<<<PHI_BLOCKS, 1024>>>(emb0, phi_w1, phi_b1, phi_w2, phi_b2);

    int nblk = (N + BN - 1) / BN;
    k_main<<<nblk, 256, SMEM_BYTES>>>(diffs, lens, filt_w, filt_b,
                                      u_w, v_w, upd_w1, upd_b1, upd_w2, upd_b2,
                                      gidx, N);

    k_out<<<G, 512>>>(out_w1, out_b1, out_w2, out_b2, out);
}